// round 16
// baseline (speedup 1.0000x reference)
#include <cuda_runtime.h>
#include <cstdint>

// Problem dims (fixed by the dataset)
#define BATCH 16384
#define DIN   1024
#define HID   2048
#define OUTD  2

// ---------------- scratch (no allocs allowed) ----------------
__device__ __align__(16) uint32_t g_Wb1[HID * 32];   // w1 bits: 2048 x (1024/32)
__device__ __align__(16) uint32_t g_Wb2[HID * 64];   // w2 bits: 2048 x (2048/32)
__device__ __align__(16) uint32_t g_Wb3[HID * 64];   // w3 bits
__device__ __align__(16) uint32_t g_Wbo[OUTD * 64];  // wout bits
__device__ float g_t1[HID], g_t2[HID], g_t3[HID];    // BN thresholds
__device__ __align__(16) uint32_t g_A[BATCH * 64];   // activation bits, buffer A
__device__ __align__(16) uint32_t g_B[BATCH * 64];   // activation bits, buffer B

// ---------------- LOP3 helpers ----------------
__device__ __forceinline__ uint32_t xor3(uint32_t a, uint32_t b, uint32_t c) {
    uint32_t r;
    asm("lop3.b32 %0, %1, %2, %3, 0x96;" : "=r"(r) : "r"(a), "r"(b), "r"(c));
    return r;
}
__device__ __forceinline__ uint32_t maj3(uint32_t a, uint32_t b, uint32_t c) {
    uint32_t r;
    asm("lop3.b32 %0, %1, %2, %3, 0xE8;" : "=r"(r) : "r"(a), "r"(b), "r"(c));
    return r;
}

// ---------------- pack floats -> sign bits -------------------
__global__ void pack_bits_kernel(const float* __restrict__ src,
                                 uint32_t* __restrict__ dst,
                                 int nbits, float thresh) {
    int i = blockIdx.x * blockDim.x + threadIdx.x;
    unsigned bit = 0u;
    if (i < nbits) bit = (src[i] >= thresh) ? 1u : 0u;
    unsigned m = __ballot_sync(0xffffffffu, bit);
    if ((threadIdx.x & 31) == 0 && i < nbits) dst[i >> 5] = m;
}

// ---------------- BN -> scalar threshold ---------------------
__global__ void thresh_kernel(const float* __restrict__ g,
                              const float* __restrict__ b,
                              const float* __restrict__ m,
                              const float* __restrict__ v,
                              float* __restrict__ t, int n) {
    int j = blockIdx.x * blockDim.x + threadIdx.x;
    if (j < n) {
        float inv = g[j] * rsqrtf(v[j] + 1e-5f);
        t[j] = m[j] - b[j] / inv;
    }
}

// ---------------- bit-GEMM layer (3:2 compressor popcount) -------
// Block: 256 threads = 8 warps; lane owns one row (256 rows/CTA), row bits in
// registers. Neuron tile = 64 (grid.y = HID/64) -> 2048 small CTAs per layer
// for near-perfect wave packing (7 waves @ 2 CTA/SM vs 2 ragged waves before).
// Counting: per 3 xor-words, s=xor3, c=maj3, popc(s) + 2*popc(c) -- exact, no
// serial carry chain (all groups independent -> max ILP). 4th word of each
// uint4 goes to a pending buffer compressed every 3 iterations.
template <int KW>  // words per input row: 32 (K=1024) or 64 (K=2048)
__global__ void __launch_bounds__(256, 2) binlayer_kernel(
    const uint32_t* __restrict__ Xb, int xstride,
    const uint32_t* __restrict__ Wb,
    const float* __restrict__ th,
    uint32_t* __restrict__ Yb, int ystride) {
    __shared__ uint4 sW4[64 * KW / 4];
    __shared__ float sT[64];

    const int lane = threadIdx.x & 31;
    const int warp = threadIdx.x >> 5;
    const int row = blockIdx.x * 256 + warp * 32 + lane;
    const int nbase = blockIdx.y * 64;

    // Stage 64 neurons' weight bits + thresholds into smem.
    const uint4* wsrc = reinterpret_cast<const uint4*>(Wb + (size_t)nbase * KW);
#pragma unroll
    for (int idx = threadIdx.x; idx < 64 * KW / 4; idx += 256)
        sW4[idx] = wsrc[idx];
    if (threadIdx.x < 64) sT[threadIdx.x] = th[nbase + threadIdx.x];

    // Load this lane's row bits into registers.
    uint32_t x[KW];
    const uint4* xr = reinterpret_cast<const uint4*>(Xb + (size_t)row * xstride);
#pragma unroll
    for (int k = 0; k < KW / 4; k++) {
        uint4 t = xr[k];
        x[4 * k + 0] = t.x; x[4 * k + 1] = t.y;
        x[4 * k + 2] = t.z; x[4 * k + 3] = t.w;
    }
    __syncthreads();

    uint32_t ow = 0;
#pragma unroll 2
    for (int j = 0; j < 64; j++) {
        const uint4* wp = &sW4[j * (KW / 4)];
        int accS0 = 0, accC0 = 0, accS1 = 0, accC1 = 0;
        uint32_t pend0 = 0, pend1 = 0;
#pragma unroll
        for (int k = 0; k < KW / 4; k++) {
            uint4 w = wp[k];  // broadcast LDS.128
            uint32_t u = x[4 * k + 0] ^ w.x;
            uint32_t v = x[4 * k + 1] ^ w.y;
            uint32_t t = x[4 * k + 2] ^ w.z;
            uint32_t q = x[4 * k + 3] ^ w.w;
            uint32_t s = xor3(u, v, t);
            uint32_t c = maj3(u, v, t);
            if (k & 1) { accS1 += __popc(s); accC1 += __popc(c); }
            else       { accS0 += __popc(s); accC0 += __popc(c); }
            // pending 4th-word compression (compile-time k%3 under full unroll)
            if (k % 3 == 0) pend0 = q;
            else if (k % 3 == 1) pend1 = q;
            else {
                uint32_t s2 = xor3(pend0, pend1, q);
                uint32_t c2 = maj3(pend0, pend1, q);
                if (k & 1) { accS1 += __popc(s2); accC1 += __popc(c2); }
                else       { accS0 += __popc(s2); accC0 += __popc(c2); }
            }
        }
        // leftovers: (KW/4)%3 pending words remain (KW=64 -> 1, KW=32 -> 2)
        if ((KW / 4) % 3 >= 1) accS0 += __popc(pend0);
        if ((KW / 4) % 3 == 2) accS1 += __popc(pend1);

        int total = accS0 + accS1 + 2 * (accC0 + accC1);
        float dot = (float)(KW * 32 - 2 * total);
        unsigned bit = (dot >= sT[j]) ? 1u : 0u;
        ow |= bit << (j & 31);
        if ((j & 31) == 31) {
            int wordi = (nbase + j) >> 5;
            Yb[(size_t)row * ystride + wordi] = ow;
            ow = 0;
        }
    }
}

// ---------------- final 2-neuron linear ----------------------
__global__ void outlayer_kernel(const uint32_t* __restrict__ Xb,
                                const uint32_t* __restrict__ Wo,
                                float* __restrict__ out) {
    int row = blockIdx.x * blockDim.x + threadIdx.x;
    if (row >= BATCH) return;
    uint32_t x[64];
    const uint4* xr = reinterpret_cast<const uint4*>(Xb + (size_t)row * 64);
#pragma unroll
    for (int k = 0; k < 16; k++) {
        uint4 t = xr[k];
        x[4 * k + 0] = t.x; x[4 * k + 1] = t.y;
        x[4 * k + 2] = t.z; x[4 * k + 3] = t.w;
    }
#pragma unroll
    for (int o = 0; o < OUTD; o++) {
        int acc = 0;
#pragma unroll
        for (int k = 0; k < 64; k++) acc += __popc(x[k] ^ Wo[o * 64 + k]);
        out[row * OUTD + o] = (float)(HID - 2 * acc);
    }
}

// ---------------- launch -------------------------------------
extern "C" void kernel_launch(void* const* d_in, const int* in_sizes, int n_in,
                              void* d_out, int out_size) {
    const float* x    = (const float*)d_in[0];
    const float* w1   = (const float*)d_in[1];
    const float* g1   = (const float*)d_in[2];
    const float* b1   = (const float*)d_in[3];
    const float* m1   = (const float*)d_in[4];
    const float* v1   = (const float*)d_in[5];
    const float* w2   = (const float*)d_in[6];
    const float* g2   = (const float*)d_in[7];
    const float* b2   = (const float*)d_in[8];
    const float* m2   = (const float*)d_in[9];
    const float* v2   = (const float*)d_in[10];
    const float* w3   = (const float*)d_in[11];
    const float* g3   = (const float*)d_in[12];
    const float* b3   = (const float*)d_in[13];
    const float* m3   = (const float*)d_in[14];
    const float* v3   = (const float*)d_in[15];
    const float* wout = (const float*)d_in[16];
    float* out = (float*)d_out;

    uint32_t *pWb1, *pWb2, *pWb3, *pWbo, *pA, *pB;
    float *pt1, *pt2, *pt3;
    cudaGetSymbolAddress((void**)&pWb1, g_Wb1);
    cudaGetSymbolAddress((void**)&pWb2, g_Wb2);
    cudaGetSymbolAddress((void**)&pWb3, g_Wb3);
    cudaGetSymbolAddress((void**)&pWbo, g_Wbo);
    cudaGetSymbolAddress((void**)&pA, g_A);
    cudaGetSymbolAddress((void**)&pB, g_B);
    cudaGetSymbolAddress((void**)&pt1, g_t1);
    cudaGetSymbolAddress((void**)&pt2, g_t2);
    cudaGetSymbolAddress((void**)&pt3, g_t3);

    // 1) binarize+pack input: 2x-1 >= 0 <=> x >= 0.5
    pack_bits_kernel<<<(BATCH * DIN) / 256, 256>>>(x, pA, BATCH * DIN, 0.5f);
    // 2) pack weights (sign bit: w >= 0)
    pack_bits_kernel<<<(HID * DIN) / 256, 256>>>(w1, pWb1, HID * DIN, 0.0f);
    pack_bits_kernel<<<(HID * HID) / 256, 256>>>(w2, pWb2, HID * HID, 0.0f);
    pack_bits_kernel<<<(HID * HID) / 256, 256>>>(w3, pWb3, HID * HID, 0.0f);
    pack_bits_kernel<<<(OUTD * HID) / 256, 256>>>(wout, pWbo, OUTD * HID, 0.0f);
    // 3) BN thresholds
    thresh_kernel<<<HID / 256, 256>>>(g1, b1, m1, v1, pt1, HID);
    thresh_kernel<<<HID / 256, 256>>>(g2, b2, m2, v2, pt2, HID);
    thresh_kernel<<<HID / 256, 256>>>(g3, b3, m3, v3, pt3, HID);

    // 4) three bit-GEMM layers (3:2 compressor popcount, fine-grain tiles)
    dim3 grid(BATCH / 256, HID / 64);
    binlayer_kernel<32><<<grid, 256>>>(pA, 32, pWb1, pt1, pB, 64);
    binlayer_kernel<64><<<grid, 256>>>(pB, 64, pWb2, pt2, pA, 64);
    binlayer_kernel<64><<<grid, 256>>>(pA, 64, pWb3, pt3, pB, 64);

    // 5) final 2-neuron linear -> float out
    outlayer_kernel<<<BATCH / 256, 256>>>(pB, pWbo, out);
}

// round 17
// speedup vs baseline: 1.3574x; 1.3574x over previous
#include <cuda_runtime.h>
#include <cstdint>

// Problem dims (fixed by the dataset)
#define BATCH 16384
#define DIN   1024
#define HID   2048
#define OUTD  2

// ---------------- scratch (no allocs allowed) ----------------
__device__ __align__(16) uint32_t g_Wb1[HID * 32];   // w1 bits: 2048 x (1024/32)
__device__ __align__(16) uint32_t g_Wb2[HID * 64];   // w2 bits: 2048 x (2048/32)
__device__ __align__(16) uint32_t g_Wb3[HID * 64];   // w3 bits
__device__ __align__(16) uint32_t g_Wbo[OUTD * 64];  // wout bits
__device__ float g_t1[HID], g_t2[HID], g_t3[HID];    // BN thresholds
__device__ __align__(16) uint32_t g_A[BATCH * 64];   // activation bits, buffer A
__device__ __align__(16) uint32_t g_B[BATCH * 64];   // activation bits, buffer B

// ---------------- LOP3 helpers (full-adder in 2 ops) ----------------
__device__ __forceinline__ uint32_t xor3(uint32_t a, uint32_t b, uint32_t c) {
    uint32_t r;
    asm("lop3.b32 %0, %1, %2, %3, 0x96;" : "=r"(r) : "r"(a), "r"(b), "r"(c));
    return r;
}
__device__ __forceinline__ uint32_t maj3(uint32_t a, uint32_t b, uint32_t c) {
    uint32_t r;
    asm("lop3.b32 %0, %1, %2, %3, 0xE8;" : "=r"(r) : "r"(a), "r"(b), "r"(c));
    return r;
}
// CSA full-adder: (state, a, b) -> state = sum, returns carry
__device__ __forceinline__ uint32_t csa(uint32_t& state, uint32_t a, uint32_t b) {
    uint32_t c = maj3(state, a, b);
    state = xor3(state, a, b);
    return c;
}

// ---------------- pack floats -> sign bits -------------------
// bit = (src[i] >= thresh). Launched with exactly nbits threads (multiple of 32).
__global__ void pack_bits_kernel(const float* __restrict__ src,
                                 uint32_t* __restrict__ dst,
                                 int nbits, float thresh) {
    int i = blockIdx.x * blockDim.x + threadIdx.x;
    unsigned bit = 0u;
    if (i < nbits) bit = (src[i] >= thresh) ? 1u : 0u;
    unsigned m = __ballot_sync(0xffffffffu, bit);
    if ((threadIdx.x & 31) == 0 && i < nbits) dst[i >> 5] = m;
}

// ---------------- BN -> scalar threshold ---------------------
// bn(dot) >= 0  <=>  dot >= m - b/inv, inv = g*rsqrt(v+eps) > 0
__global__ void thresh_kernel(const float* __restrict__ g,
                              const float* __restrict__ b,
                              const float* __restrict__ m,
                              const float* __restrict__ v,
                              float* __restrict__ t, int n) {
    int j = blockIdx.x * blockDim.x + threadIdx.x;
    if (j < n) {
        float inv = g[j] * rsqrtf(v[j] + 1e-5f);
        t[j] = m[j] - b[j] / inv;
    }
}

// ---------------- bit-GEMM layer (depth-2 Harley-Seal popcount) -------
// Structure identical to the measured-good 959us kernel: 256 threads = 8 warps,
// lane owns one row, 256-neuron tile staged in 2 chunks of 128, grid (64, 8),
// no min-blocks clause (avoid the reg cap that spilled in R16).
// Counting: per uint4 (4 xor-words) and per unit: 2 ones-level FAs + 1
// twos-level FA -> ONE popc of the weight-4 carry. Exact:
//   total = 4*Sum popc(c4) + 2*popc(twos) + popc(ones)
// Two independent units (even/odd k) break the FA dependency chains.
template <int KW>  // words per input row: 32 (K=1024) or 64 (K=2048)
__global__ void __launch_bounds__(256) binlayer_kernel(
    const uint32_t* __restrict__ Xb, int xstride,
    const uint32_t* __restrict__ Wb,
    const float* __restrict__ th,
    uint32_t* __restrict__ Yb, int ystride) {
    __shared__ uint4 sW4[128 * KW / 4];
    __shared__ float sT[128];

    const int lane = threadIdx.x & 31;
    const int warp = threadIdx.x >> 5;
    const int row = blockIdx.x * 256 + warp * 32 + lane;
    const int nbase = blockIdx.y * 256;

    // Load this lane's row bits into registers.
    uint32_t x[KW];
    const uint4* xr = reinterpret_cast<const uint4*>(Xb + (size_t)row * xstride);
#pragma unroll
    for (int k = 0; k < KW / 4; k++) {
        uint4 t = xr[k];
        x[4 * k + 0] = t.x; x[4 * k + 1] = t.y;
        x[4 * k + 2] = t.z; x[4 * k + 3] = t.w;
    }

    uint32_t ow = 0;
#pragma unroll 1
    for (int c = 0; c < 2; c++) {
        __syncthreads();
        // Cooperative stage of 128 neurons' weight bits into smem.
        const uint4* wsrc =
            reinterpret_cast<const uint4*>(Wb + (size_t)(nbase + c * 128) * KW);
#pragma unroll
        for (int idx = threadIdx.x; idx < 128 * KW / 4; idx += 256)
            sW4[idx] = wsrc[idx];
        if (threadIdx.x < 128) sT[threadIdx.x] = th[nbase + c * 128 + threadIdx.x];
        __syncthreads();

#pragma unroll 1
        for (int j = 0; j < 128; j++) {
            const uint4* wp = &sW4[j * (KW / 4)];
            // Two independent depth-2 Harley-Seal units (even/odd k)
            uint32_t onesA = 0, twosA = 0, onesB = 0, twosB = 0;
            int acc4a = 0, acc4b = 0;
#pragma unroll
            for (int k = 0; k < KW / 4; k++) {
                uint4 w = wp[k];  // broadcast LDS.128
                uint32_t u = x[4 * k + 0] ^ w.x;
                uint32_t v = x[4 * k + 1] ^ w.y;
                uint32_t t = x[4 * k + 2] ^ w.z;
                uint32_t q = x[4 * k + 3] ^ w.w;
                if (k & 1) {
                    uint32_t c1 = csa(onesB, u, v);
                    uint32_t c2 = csa(onesB, t, q);
                    uint32_t c4 = csa(twosB, c1, c2);
                    acc4b += __popc(c4);
                } else {
                    uint32_t c1 = csa(onesA, u, v);
                    uint32_t c2 = csa(onesA, t, q);
                    uint32_t c4 = csa(twosA, c1, c2);
                    acc4a += __popc(c4);
                }
            }
            int total = 4 * (acc4a + acc4b)
                      + 2 * (__popc(twosA) + __popc(twosB))
                      + __popc(onesA) + __popc(onesB);
            float dot = (float)(KW * 32 - 2 * total);
            unsigned bit = (dot >= sT[j]) ? 1u : 0u;
            ow |= bit << (j & 31);
            if ((j & 31) == 31) {
                int wordi = (nbase + c * 128 + j) >> 5;
                Yb[(size_t)row * ystride + wordi] = ow;
                ow = 0;
            }
        }
    }
}

// ---------------- final 2-neuron linear ----------------------
__global__ void outlayer_kernel(const uint32_t* __restrict__ Xb,
                                const uint32_t* __restrict__ Wo,
                                float* __restrict__ out) {
    int row = blockIdx.x * blockDim.x + threadIdx.x;
    if (row >= BATCH) return;
    uint32_t x[64];
    const uint4* xr = reinterpret_cast<const uint4*>(Xb + (size_t)row * 64);
#pragma unroll
    for (int k = 0; k < 16; k++) {
        uint4 t = xr[k];
        x[4 * k + 0] = t.x; x[4 * k + 1] = t.y;
        x[4 * k + 2] = t.z; x[4 * k + 3] = t.w;
    }
#pragma unroll
    for (int o = 0; o < OUTD; o++) {
        int acc = 0;
#pragma unroll
        for (int k = 0; k < 64; k++) acc += __popc(x[k] ^ Wo[o * 64 + k]);
        out[row * OUTD + o] = (float)(HID - 2 * acc);
    }
}

// ---------------- launch -------------------------------------
extern "C" void kernel_launch(void* const* d_in, const int* in_sizes, int n_in,
                              void* d_out, int out_size) {
    const float* x    = (const float*)d_in[0];
    const float* w1   = (const float*)d_in[1];
    const float* g1   = (const float*)d_in[2];
    const float* b1   = (const float*)d_in[3];
    const float* m1   = (const float*)d_in[4];
    const float* v1   = (const float*)d_in[5];
    const float* w2   = (const float*)d_in[6];
    const float* g2   = (const float*)d_in[7];
    const float* b2   = (const float*)d_in[8];
    const float* m2   = (const float*)d_in[9];
    const float* v2   = (const float*)d_in[10];
    const float* w3   = (const float*)d_in[11];
    const float* g3   = (const float*)d_in[12];
    const float* b3   = (const float*)d_in[13];
    const float* m3   = (const float*)d_in[14];
    const float* v3   = (const float*)d_in[15];
    const float* wout = (const float*)d_in[16];
    float* out = (float*)d_out;

    uint32_t *pWb1, *pWb2, *pWb3, *pWbo, *pA, *pB;
    float *pt1, *pt2, *pt3;
    cudaGetSymbolAddress((void**)&pWb1, g_Wb1);
    cudaGetSymbolAddress((void**)&pWb2, g_Wb2);
    cudaGetSymbolAddress((void**)&pWb3, g_Wb3);
    cudaGetSymbolAddress((void**)&pWbo, g_Wbo);
    cudaGetSymbolAddress((void**)&pA, g_A);
    cudaGetSymbolAddress((void**)&pB, g_B);
    cudaGetSymbolAddress((void**)&pt1, g_t1);
    cudaGetSymbolAddress((void**)&pt2, g_t2);
    cudaGetSymbolAddress((void**)&pt3, g_t3);

    // 1) binarize+pack input: 2x-1 >= 0 <=> x >= 0.5
    pack_bits_kernel<<<(BATCH * DIN) / 256, 256>>>(x, pA, BATCH * DIN, 0.5f);
    // 2) pack weights (sign bit: w >= 0)
    pack_bits_kernel<<<(HID * DIN) / 256, 256>>>(w1, pWb1, HID * DIN, 0.0f);
    pack_bits_kernel<<<(HID * HID) / 256, 256>>>(w2, pWb2, HID * HID, 0.0f);
    pack_bits_kernel<<<(HID * HID) / 256, 256>>>(w3, pWb3, HID * HID, 0.0f);
    pack_bits_kernel<<<(OUTD * HID) / 256, 256>>>(wout, pWbo, OUTD * HID, 0.0f);
    // 3) BN thresholds
    thresh_kernel<<<HID / 256, 256>>>(g1, b1, m1, v1, pt1, HID);
    thresh_kernel<<<HID / 256, 256>>>(g2, b2, m2, v2, pt2, HID);
    thresh_kernel<<<HID / 256, 256>>>(g3, b3, m3, v3, pt3, HID);

    // 4) three bit-GEMM layers (depth-2 Harley-Seal popcount)
    dim3 grid(BATCH / 256, HID / 256);
    binlayer_kernel<32><<<grid, 256>>>(pA, 32, pWb1, pt1, pB, 64);
    binlayer_kernel<64><<<grid, 256>>>(pB, 64, pWb2, pt2, pA, 64);
    binlayer_kernel<64><<<grid, 256>>>(pA, 64, pWb3, pt3, pB, 64);

    // 5) final 2-neuron linear -> float out
    outlayer_kernel<<<BATCH / 256, 256>>>(pB, pWbo, out);
}